// round 15
// baseline (speedup 1.0000x reference)
#include <cuda_runtime.h>

// B=2048 rows, N=8192 cols. PERSISTENT kernel: 444 CTAs (3/SM) x 512 thr;
// CTA c handles rows c, c+444, ... with next-row L2 prefetch.
//
// Round-15: residuals live in SHARED memory (r4s[4][512], 32KB/CTA) instead
// of 16 registers, cutting the register footprint so THREE CTAs fit per SM
// (launch_bounds(512,3) -> 42-reg cap). r4s is only ever accessed at [c][t]
// by thread t (round-1 write, polish read, epilogue read) => thread-private
// slots, no cross-thread hazards, no extra barriers. Higher residency =
// more outstanding loads per SM = higher DRAM utilization (was 58%, the
// kernel is pure memory-time: 4.6TB/s x 54.6us = exactly the 256MB
// compulsory traffic).
//
// Solver (unchanged from round 14): inputs i.i.d. => residual scale is
// global; half-normal moment equation gives universal root v*=0.8435 =>
// CONSTANT init beta_c = v*/sqrt(2) = 0.59645, ~1% from each row's root.
// One barrier round jointly reduces rmax, S=sum(e^x-e^-x), T=sum r(e^x+e^-x)
// at x=beta_c*r; one clamped Newton step on h=log(S)-ln(2N) => ~1e-4 rel
// (quadratic), exit at 2e-2 threshold; adaptive extra rounds (10 budget) if
// data ever violates the assumption - init quality affects speed only.
// Same unique root as the reference's 20 eps-space Newton iterations.
// eps=1/beta (floored), betaF=1/(eps+1e-6) per reference; q=sinh(betaF*r);
// qmax=sinh(betaF*rmax) (sinh monotone on r>=0);
// Lambda' = 0.99*Lambda + 0.09*q/(qmax+1e-20) + 0.01 (folded constants).
// Loss: per-thread register accumulator across rows; one end-of-kernel block
// reduction -> g_cta_loss; last CTA (fence+counter, self-resetting for graph
// replays) reduces 444 partials in fixed order => deterministic.
// Output: d_out[0]=loss, d_out[1..B*N]=Lambda' (row-major).

#define BDIM 512
#define VPT 16
#define NWARP (BDIM / 32)   // 16
#define NCTA 444            // 3 CTAs per SM x 148 SMs

static constexpr int B = 2048;
static constexpr int N = 8192;
static constexpr float LOG_2N = 9.70406052783923f;  // ln(2*N) = ln(16384)
static constexpr float BETA_C = 0.59645f;           // v*/sqrt(2), v*=0.8435

__device__ float g_cta_loss[NCTA];
__device__ unsigned int g_count = 0;

__device__ __forceinline__ float warp_sum(float v) {
#pragma unroll
    for (int o = 16; o; o >>= 1) v += __shfl_xor_sync(0xffffffffu, v, o);
    return v;
}
__device__ __forceinline__ float warp_max(float v) {
#pragma unroll
    for (int o = 16; o; o >>= 1) v = fmaxf(v, __shfl_xor_sync(0xffffffffu, v, o));
    return v;
}

__global__ __launch_bounds__(BDIM, 3)
void custom_loss_row_kernel(const float* __restrict__ y_pred,
                            const float* __restrict__ y_true,
                            const float* __restrict__ Lam,
                            float* __restrict__ out_lambda,
                            float* __restrict__ out_loss) {
    const int t = threadIdx.x;
    const int lane = t & 31;
    const int wid = t >> 5;

    __shared__ float4 r4s[4][BDIM];   // residuals, thread-private slots
    __shared__ float s1s[32];         // 16 warp partials + 16 zero-pad
    __shared__ float s2s[32];
    __shared__ float s3s[32];
    __shared__ float bc_beta;
    __shared__ float bc_max;
    __shared__ int   sdone;
    __shared__ int   amLast;

    // zero-pad slots 16..31 once (neutral for max since r>=0 and for sums;
    // wid<16 so never rewritten). Visible after the first barrier.
    if (t >= NWARP && t < 32) { s1s[t] = 0.0f; s2s[t] = 0.0f; s3s[t] = 0.0f; }

    float loss_acc = 0.0f;  // per-thread, across all this CTA's rows

#pragma unroll 1
    for (int row = blockIdx.x; row < B; row += NCTA) {
        const size_t base = (size_t)row * N;
        const float4* yp4 = (const float4*)(y_pred + base);
        const float4* yt4 = (const float4*)(y_true + base);

        // ---- round 1: residuals -> smem, plus rmax/S/T in one pass ----
        float m = 0.0f, S = 0.0f, T = 0.0f;
#pragma unroll
        for (int c = 0; c < 4; c++) {
            const float4 p = yp4[t + c * BDIM];
            const float4 g = yt4[t + c * BDIM];
            float4 rv;
            rv.x = fabsf(g.x - p.x);
            rv.y = fabsf(g.y - p.y);
            rv.z = fabsf(g.z - p.z);
            rv.w = fabsf(g.w - p.w);
            r4s[c][t] = rv;
            const float rr[4] = {rv.x, rv.y, rv.z, rv.w};
#pragma unroll
            for (int i = 0; i < 4; i++) {
                m = fmaxf(m, rr[i]);
                const float x  = BETA_C * rr[i];
                const float E  = __expf(x);
                const float Em = __expf(-x);
                S += (E - Em);
                T = fmaf(E + Em, rr[i], T);
            }
        }

        // ---- L2-prefetch the NEXT row (yp/yt/Lam; one 128B line per slot)
        {
            const int nrow = row + NCTA;
            if (nrow < B) {
                const size_t nb = (size_t)nrow * N;
                if (t < 256) {
                    asm volatile("prefetch.global.L2 [%0];" ::
                                 "l"(y_pred + nb + (size_t)t * 32));
                    asm volatile("prefetch.global.L2 [%0];" ::
                                 "l"(Lam + nb + (size_t)t * 32));
                } else {
                    asm volatile("prefetch.global.L2 [%0];" ::
                                 "l"(y_true + nb + (size_t)(t - 256) * 32));
                }
            }
        }

        m = warp_max(m);
        S = warp_sum(S);
        T = warp_sum(T);
        if (lane == 0) { s1s[wid] = m; s2s[wid] = S; s3s[wid] = T; }
        __syncthreads();
        if (t < 32) {
            const float vm = warp_max(s1s[lane]);  // full warp, full-mask
            const float S2 = warp_sum(s2s[lane]);
            const float T2 = warp_sum(s3s[lane]);
            if (t == 0) {
                const float h  = __logf(S2) - LOG_2N;
                const float db = h * __fdividef(S2, T2);
                float nb = BETA_C - db;
                bc_beta = fminf(fmaxf(nb, 0.05f * BETA_C), 4.0f * BETA_C);
                bc_max  = vm;
                sdone   = (fabsf(db) < 2e-2f * BETA_C) ? 1 : 0;
            }
        }
        __syncthreads();
        float beta = bc_beta;
        const float rmax = bc_max;

        // ---- adaptive extra polish (normally skipped entirely) ----
        if (!sdone) {
#pragma unroll 1
            for (int itn = 0; itn < 10; itn++) {
                float Sa = 0.0f, Ta = 0.0f;
#pragma unroll
                for (int c = 0; c < 4; c++) {
                    const float4 rv = r4s[c][t];
                    const float rr[4] = {rv.x, rv.y, rv.z, rv.w};
#pragma unroll
                    for (int i = 0; i < 4; i++) {
                        const float x  = beta * rr[i];
                        const float E  = __expf(x);
                        const float Em = __expf(-x);
                        Sa += (E - Em);
                        Ta = fmaf(E + Em, rr[i], Ta);
                    }
                }
                Sa = warp_sum(Sa);
                Ta = warp_sum(Ta);
                if (lane == 0) { s2s[wid] = Sa; s3s[wid] = Ta; }
                __syncthreads();
                if (t < 32) {
                    const float S2 = warp_sum(s2s[lane]);
                    const float T2 = warp_sum(s3s[lane]);
                    if (t == 0) {
                        const float h  = __logf(S2) - LOG_2N;
                        const float db = h * __fdividef(S2, T2);
                        float nb = beta - db;
                        bc_beta = fminf(fmaxf(nb, 0.05f * beta), 4.0f * beta);
                        sdone = (fabsf(db) < 2e-2f * beta) ? 1 : 0;
                    }
                }
                __syncthreads();
                beta = bc_beta;
                if (sdone) break;  // uniform across block
            }
        }

        // ---- final beta exactly as reference: eps floor, then +1e-6 ----
        const float eps = fmaxf(__fdividef(1.0f, beta), 1e-8f);
        const float betaF = __fdividef(1.0f, eps + 1e-6f);

        // qmax analytically: sinh monotone on r>=0 -> max at rmax
        const float xm = betaF * rmax;
        const float qmax = 0.5f * (__expf(xm) - __expf(-xm));
        // lam = 0.99*L + 0.09*(0.5*(E-Em)/(qmax+1e-20)) + 0.01
        //     = fmaf(0.99, L, fmaf(c1, E-Em, 0.01)),  c1 = 0.045/(qmax+1e-20)
        const float c1 = __fdividef(0.045f, qmax + 1e-20f);

        // ---- epilogue: q, Lambda update, loss into register accumulator.
        //      No barrier needed: r4s[c][t] is read by the same thread that
        //      wrote it, and next row's overwrite is by that thread too. ----
        const float4* L4 = (const float4*)(Lam + base);
#pragma unroll
        for (int c = 0; c < 4; c++) {
            const float4 rv = r4s[c][t];
            const float4 l  = L4[t + c * BDIM];
            const float rr[4] = {rv.x, rv.y, rv.z, rv.w};
            const float la[4] = {l.x, l.y, l.z, l.w};
#pragma unroll
            for (int i = 0; i < 4; i++) {
                const float x  = betaF * rr[i];
                const float E  = __expf(x);
                const float Em = __expf(-x);
                const float lam = fmaf(0.99f, la[i], fmaf(c1, E - Em, 0.01f));
                out_lambda[base + 4 * (t + c * BDIM) + i] = lam;
                const float z = lam * rr[i];
                loss_acc = fmaf(z, z, loss_acc);
            }
        }
    }

    // ---- end of rows: one block reduction of the register accumulator ----
    {
        float ls = warp_sum(loss_acc);
        __syncthreads();  // prior round's warp0 reads done before reuse
        if (lane == 0) s1s[wid] = ls;
        __syncthreads();
        if (t == 0) {
            float v = 0.0f;
#pragma unroll
            for (int i = 0; i < NWARP; i++) v += s1s[i];
            g_cta_loss[blockIdx.x] = v;
        }
    }

    // ---- fused final reduction: last CTA reduces 444 partials, fixed order
    if (t == 0) {
        __threadfence();
        const unsigned int v = atomicAdd(&g_count, 1u);
        amLast = (v == (unsigned int)(NCTA - 1));
    }
    __syncthreads();
    if (amLast) {
        float s = (t < NCTA) ? g_cta_loss[t] : 0.0f;
        s = warp_sum(s);
        if (lane == 0) s2s[wid] = s;   // 16 partials; slots 16..31 still 0
        __syncthreads();
        if (t < 32) {
            const float v = warp_sum(s2s[lane]);
            if (t == 0) {
                out_loss[0] = v * (1.0f / 16777216.0f);  // / (B*N)
                g_count = 0;  // reset for the next launch / graph replay
            }
        }
    }
}

extern "C" void kernel_launch(void* const* d_in, const int* in_sizes, int n_in,
                              void* d_out, int out_size) {
    const float* y_pred = (const float*)d_in[0];
    const float* y_true = (const float*)d_in[1];
    const float* Lam    = (const float*)d_in[2];
    // d_in[3] = it (unused by the cosh branch)

    float* out = (float*)d_out;       // out[0] = loss
    float* out_lambda = out + 1;      // out[1..] = updated Lambda

    custom_loss_row_kernel<<<NCTA, BDIM>>>(y_pred, y_true, Lam, out_lambda, out);
}

// round 16
// speedup vs baseline: 1.1001x; 1.1001x over previous
#include <cuda_runtime.h>
#include <cstdint>

// B=2048 rows, N=8192 cols. PERSISTENT kernel: 296 CTAs (2/SM) x 512 thr;
// CTA c handles rows c, c+296, ...
//
// Round-16: yp/yt for the NEXT row are staged into a 64KB smem buffer with
// guaranteed cp.async.cg (LDGSTS) copies instead of droppable L2-prefetch
// hints. Each thread copies exactly the float4 slots it alone will read
// (self-partition) -> issue right after extracting the current row's r, no
// extra barrier; cp.async.wait_group 0 at row top is sufficient. This keeps
// the DRAM read stream busy through the solver round (R14 showed DRAM idle
// ~40% with phase-aligned CTAs). Lambda keeps the L2-prefetch path.
//
// Solver (unchanged, R14): inputs i.i.d. => residual scale global; the
// half-normal moment equation gives universal root v*=0.8435 => CONSTANT
// init beta_c = v*/sqrt(2) = 0.59645, ~1% from each row's root. One barrier
// round jointly reduces rmax, S=sum(e^x-e^-x), T=sum r(e^x+e^-x) at
// x=beta_c*r; one clamped Newton step on h=log(S)-ln(2N) => ~1e-4 rel
// (quadratic, db applied before exit), 2e-2 threshold; adaptive extra
// rounds (10 budget) if data violates the assumption - init quality affects
// speed only, never correctness. Same unique root as the reference's 20
// eps-space Newton iterations. eps=1/beta (floored), betaF=1/(eps+1e-6) per
// reference; q=sinh(betaF*r); qmax=sinh(betaF*rmax) (sinh monotone, r>=0);
// Lambda' = 0.99*Lambda + 0.09*q/(qmax+1e-20) + 0.01 (folded constants).
// Loss: per-thread register accumulator across rows; one end block
// reduction -> g_cta_loss; last CTA (fence+counter, self-resetting for
// graph replays) reduces 296 partials in fixed order => deterministic.
// Output: d_out[0]=loss, d_out[1..B*N]=Lambda' (row-major).

#define BDIM 512
#define VPT 16
#define NWARP (BDIM / 32)   // 16
#define NCTA 296            // 2 CTAs per SM x 148 SMs
#define NF4  2048           // float4s per row (8192 floats)

static constexpr int B = 2048;
static constexpr int N = 8192;
static constexpr float LOG_2N = 9.70406052783923f;  // ln(2*N) = ln(16384)
static constexpr float BETA_C = 0.59645f;           // v*/sqrt(2), v*=0.8435

__device__ float g_cta_loss[NCTA];
__device__ unsigned int g_count = 0;

__device__ __forceinline__ float warp_sum(float v) {
#pragma unroll
    for (int o = 16; o; o >>= 1) v += __shfl_xor_sync(0xffffffffu, v, o);
    return v;
}
__device__ __forceinline__ float warp_max(float v) {
#pragma unroll
    for (int o = 16; o; o >>= 1) v = fmaxf(v, __shfl_xor_sync(0xffffffffu, v, o));
    return v;
}
__device__ __forceinline__ uint32_t smem_u32(const void* p) {
    uint32_t a;
    asm("{ .reg .u64 t; cvta.to.shared.u64 t, %1; cvt.u32.u64 %0, t; }"
        : "=r"(a) : "l"(p));
    return a;
}
__device__ __forceinline__ void cp16(uint32_t dst, const void* src) {
    asm volatile("cp.async.cg.shared.global [%0], [%1], 16;"
                 :: "r"(dst), "l"(src));
}

__global__ __launch_bounds__(BDIM, 2)
void custom_loss_row_kernel(const float* __restrict__ y_pred,
                            const float* __restrict__ y_true,
                            const float* __restrict__ Lam,
                            float* __restrict__ out_lambda,
                            float* __restrict__ out_loss) {
    const int t = threadIdx.x;
    const int lane = t & 31;
    const int wid = t >> 5;

    extern __shared__ float4 dbuf[];           // [0..NF4) yp, [NF4..2NF4) yt
    float4* byp = dbuf;
    float4* byt = dbuf + NF4;
    const uint32_t byp_u32 = smem_u32(byp);
    const uint32_t byt_u32 = byp_u32 + NF4 * 16;

    __shared__ float s1s[32];   // 16 warp partials + 16 zero-pad
    __shared__ float s2s[32];
    __shared__ float s3s[32];
    __shared__ float bc_beta;
    __shared__ float bc_max;
    __shared__ int   sdone;
    __shared__ int   amLast;

    // zero-pad slots 16..31 once (neutral for max since r>=0 and for sums;
    // wid<16 so never rewritten). Visible after the first barrier.
    if (t >= NWARP && t < 32) { s1s[t] = 0.0f; s2s[t] = 0.0f; s3s[t] = 0.0f; }

    // ---- prologue: stage the first row's yp/yt (self-partition) ----
    {
        const size_t nb4 = (size_t)blockIdx.x * (N / 4);
        const float4* gyp = (const float4*)y_pred + nb4;
        const float4* gyt = (const float4*)y_true + nb4;
#pragma unroll
        for (int c = 0; c < 4; c++) {
            const int idx = t + c * BDIM;
            cp16(byp_u32 + idx * 16, gyp + idx);
            cp16(byt_u32 + idx * 16, gyt + idx);
        }
        asm volatile("cp.async.commit_group;" ::: "memory");
    }

    float loss_acc = 0.0f;  // per-thread, across all this CTA's rows

#pragma unroll 1
    for (int row = blockIdx.x; row < B; row += NCTA) {
        const size_t base = (size_t)row * N;

        // ---- wait for my own staged copies, extract r to registers ----
        asm volatile("cp.async.wait_group 0;" ::: "memory");
        float r[VPT];
#pragma unroll
        for (int c = 0; c < 4; c++) {
            const float4 p = byp[t + c * BDIM];
            const float4 g = byt[t + c * BDIM];
            r[4 * c + 0] = fabsf(g.x - p.x);
            r[4 * c + 1] = fabsf(g.y - p.y);
            r[4 * c + 2] = fabsf(g.z - p.z);
            r[4 * c + 3] = fabsf(g.w - p.w);
        }

        // ---- earliest safe point: stage NEXT row (this thread's slots
        //      only were read above by this thread) + prefetch Lam ----
        {
            const int nrow = row + NCTA;
            if (nrow < B) {
                const size_t nb4 = (size_t)nrow * (N / 4);
                const float4* gyp = (const float4*)y_pred + nb4;
                const float4* gyt = (const float4*)y_true + nb4;
#pragma unroll
                for (int c = 0; c < 4; c++) {
                    const int idx = t + c * BDIM;
                    cp16(byp_u32 + idx * 16, gyp + idx);
                    cp16(byt_u32 + idx * 16, gyt + idx);
                }
                asm volatile("cp.async.commit_group;" ::: "memory");
                if (t < 256) {
                    asm volatile("prefetch.global.L2 [%0];" ::
                                 "l"(Lam + (size_t)nrow * N + (size_t)t * 32));
                }
            }
        }

        // ---- THE barrier round: rmax + S,T at the constant init beta_c ----
        float m = 0.0f, S = 0.0f, T = 0.0f;
#pragma unroll
        for (int i = 0; i < VPT; i++) {
            m = fmaxf(m, r[i]);
            const float x  = BETA_C * r[i];
            const float E  = __expf(x);
            const float Em = __expf(-x);
            S += (E - Em);
            T = fmaf(E + Em, r[i], T);
        }
        m = warp_max(m);
        S = warp_sum(S);
        T = warp_sum(T);
        if (lane == 0) { s1s[wid] = m; s2s[wid] = S; s3s[wid] = T; }
        __syncthreads();
        if (t < 32) {
            const float vm = warp_max(s1s[lane]);  // full warp, full-mask
            const float S2 = warp_sum(s2s[lane]);
            const float T2 = warp_sum(s3s[lane]);
            if (t == 0) {
                const float h  = __logf(S2) - LOG_2N;
                const float db = h * __fdividef(S2, T2);
                float nb = BETA_C - db;
                bc_beta = fminf(fmaxf(nb, 0.05f * BETA_C), 4.0f * BETA_C);
                bc_max  = vm;
                sdone   = (fabsf(db) < 2e-2f * BETA_C) ? 1 : 0;
            }
        }
        __syncthreads();
        float beta = bc_beta;
        const float rmax = bc_max;

        // ---- adaptive extra polish (normally skipped entirely) ----
        if (!sdone) {
#pragma unroll 1
            for (int itn = 0; itn < 10; itn++) {
                float Sa = 0.0f, Ta = 0.0f;
#pragma unroll
                for (int i = 0; i < VPT; i++) {
                    const float x  = beta * r[i];
                    const float E  = __expf(x);
                    const float Em = __expf(-x);
                    Sa += (E - Em);
                    Ta = fmaf(E + Em, r[i], Ta);
                }
                Sa = warp_sum(Sa);
                Ta = warp_sum(Ta);
                if (lane == 0) { s2s[wid] = Sa; s3s[wid] = Ta; }
                __syncthreads();
                if (t < 32) {
                    const float S2 = warp_sum(s2s[lane]);
                    const float T2 = warp_sum(s3s[lane]);
                    if (t == 0) {
                        const float h  = __logf(S2) - LOG_2N;
                        const float db = h * __fdividef(S2, T2);
                        float nb = beta - db;
                        bc_beta = fminf(fmaxf(nb, 0.05f * beta), 4.0f * beta);
                        sdone = (fabsf(db) < 2e-2f * beta) ? 1 : 0;
                    }
                }
                __syncthreads();
                beta = bc_beta;
                if (sdone) break;  // uniform across block
            }
        }

        // ---- final beta exactly as reference: eps floor, then +1e-6 ----
        const float eps = fmaxf(__fdividef(1.0f, beta), 1e-8f);
        const float betaF = __fdividef(1.0f, eps + 1e-6f);

        // qmax analytically: sinh monotone on r>=0 -> max at rmax
        const float xm = betaF * rmax;
        const float qmax = 0.5f * (__expf(xm) - __expf(-xm));
        // lam = fmaf(0.99, L, fmaf(c1, E-Em, 0.01)),  c1 = 0.045/(qmax+1e-20)
        const float c1 = __fdividef(0.045f, qmax + 1e-20f);

        // ---- epilogue: q, Lambda update, loss into register accumulator ----
        // (float4 Lambda loads, L2-hit; scalar stores: out base is +1 float)
        const float4* L4 = (const float4*)(Lam + base);
        float lsum_local = 0.0f;
#pragma unroll
        for (int c = 0; c < 4; c++) {
            const float4 l = L4[t + c * BDIM];
            const float la[4] = {l.x, l.y, l.z, l.w};
#pragma unroll
            for (int i = 0; i < 4; i++) {
                const float rv = r[4 * c + i];
                const float x  = betaF * rv;
                const float E  = __expf(x);
                const float Em = __expf(-x);
                const float lam = fmaf(0.99f, la[i], fmaf(c1, E - Em, 0.01f));
                out_lambda[base + 4 * (t + c * BDIM) + i] = lam;
                const float z = lam * rv;
                lsum_local = fmaf(z, z, lsum_local);
            }
        }
        loss_acc += lsum_local;
    }

    // ---- end of rows: one block reduction of the register accumulator ----
    {
        float ls = warp_sum(loss_acc);
        __syncthreads();  // prior round's warp0 reads done before reuse
        if (lane == 0) s1s[wid] = ls;
        __syncthreads();
        if (t == 0) {
            float v = 0.0f;
#pragma unroll
            for (int i = 0; i < NWARP; i++) v += s1s[i];
            g_cta_loss[blockIdx.x] = v;
        }
    }

    // ---- fused final reduction: last CTA reduces 296 partials, fixed order
    if (t == 0) {
        __threadfence();
        const unsigned int v = atomicAdd(&g_count, 1u);
        amLast = (v == (unsigned int)(NCTA - 1));
    }
    __syncthreads();
    if (amLast) {
        float s = (t < NCTA) ? g_cta_loss[t] : 0.0f;
        s = warp_sum(s);
        if (lane == 0) s2s[wid] = s;   // 16 partials; slots 16..31 still 0
        __syncthreads();
        if (t < 32) {
            const float v = warp_sum(s2s[lane]);
            if (t == 0) {
                out_loss[0] = v * (1.0f / 16777216.0f);  // / (B*N)
                g_count = 0;  // reset for the next launch / graph replay
            }
        }
    }
}

extern "C" void kernel_launch(void* const* d_in, const int* in_sizes, int n_in,
                              void* d_out, int out_size) {
    const float* y_pred = (const float*)d_in[0];
    const float* y_true = (const float*)d_in[1];
    const float* Lam    = (const float*)d_in[2];
    // d_in[3] = it (unused by the cosh branch)

    float* out = (float*)d_out;       // out[0] = loss
    float* out_lambda = out + 1;      // out[1..] = updated Lambda

    const int dyn_smem = 2 * NF4 * 16;  // 64 KB (yp + yt staging)
    cudaFuncSetAttribute(custom_loss_row_kernel,
                         cudaFuncAttributeMaxDynamicSharedMemorySize, dyn_smem);
    custom_loss_row_kernel<<<NCTA, BDIM, dyn_smem>>>(y_pred, y_true, Lam,
                                                     out_lambda, out);
}

// round 17
// speedup vs baseline: 1.1212x; 1.0192x over previous
#include <cuda_runtime.h>
#include <cstdint>

// B=2048 rows, N=8192 cols. PERSISTENT kernel: 296 CTAs (2/SM) x 512 thr;
// CTA c handles rows c, c+296, ...
//
// Round-17 memory plumbing:
//  * yp/yt AND Lam staged one row ahead with guaranteed cp.async.cg into a
//    96KB smem triple buffer (self-partitioned slots -> no barriers). Two
//    commit groups per row (y, Lam); wait_group 1 at each consume point
//    (commit order makes "all but newest" = the needed group); wait_group 0
//    on the last row. Epilogue touches only smem: no exposed L2 latency.
//  * Stores vectorized despite the +1 misalignment: the thread owning cols
//    4j..4j+3 builds the ALIGNED float4 at out offset 4j+4 =
//    {my lam3, next-lane lam0,lam1,lam2} via 3 shfl_down; lane 0 patches 3
//    scalars (its lam0..2), lane 31 one scalar (its lam3). Streaming .cs
//    hints keep L2 for the read streams.
//
// Solver (unchanged): inputs i.i.d. => residual scale global; half-normal
// moment equation gives universal root v*=0.8435 => CONSTANT init
// beta_c = v*/sqrt(2) = 0.59645, ~1% from each row's root. One barrier round
// jointly reduces rmax, S=sum(e^x-e^-x), T=sum r(e^x+e^-x) at x=beta_c*r;
// one clamped Newton step on h=log(S)-ln(2N) => ~1e-4 rel (quadratic, db
// applied before exit), 2e-2 threshold; adaptive extra rounds (10 budget) if
// data violates the assumption - init quality affects speed only, never
// correctness. Same unique root as the reference's 20 eps-space iterations.
// eps=1/beta (floored), betaF=1/(eps+1e-6) per reference; q=sinh(betaF*r);
// qmax=sinh(betaF*rmax) (sinh monotone, r>=0);
// Lambda' = 0.99*Lambda + 0.09*q/(qmax+1e-20) + 0.01 (folded constants).
// Loss: per-thread register accumulator across rows; one end block
// reduction -> g_cta_loss; last CTA (fence+counter, self-resetting for graph
// replays) reduces 296 partials in fixed order => deterministic.
// Output: d_out[0]=loss, d_out[1..B*N]=Lambda' (row-major).

#define BDIM 512
#define VPT 16
#define NWARP (BDIM / 32)   // 16
#define NCTA 296            // 2 CTAs per SM x 148 SMs
#define NF4  2048           // float4s per row (8192 floats)

static constexpr int B = 2048;
static constexpr int N = 8192;
static constexpr float LOG_2N = 9.70406052783923f;  // ln(2*N) = ln(16384)
static constexpr float BETA_C = 0.59645f;           // v*/sqrt(2), v*=0.8435

__device__ float g_cta_loss[NCTA];
__device__ unsigned int g_count = 0;

__device__ __forceinline__ float warp_sum(float v) {
#pragma unroll
    for (int o = 16; o; o >>= 1) v += __shfl_xor_sync(0xffffffffu, v, o);
    return v;
}
__device__ __forceinline__ float warp_max(float v) {
#pragma unroll
    for (int o = 16; o; o >>= 1) v = fmaxf(v, __shfl_xor_sync(0xffffffffu, v, o));
    return v;
}
__device__ __forceinline__ uint32_t smem_u32(const void* p) {
    uint32_t a;
    asm("{ .reg .u64 t; cvta.to.shared.u64 t, %1; cvt.u32.u64 %0, t; }"
        : "=r"(a) : "l"(p));
    return a;
}
__device__ __forceinline__ void cp16(uint32_t dst, const void* src) {
    asm volatile("cp.async.cg.shared.global [%0], [%1], 16;"
                 :: "r"(dst), "l"(src));
}

__global__ __launch_bounds__(BDIM, 2)
void custom_loss_row_kernel(const float* __restrict__ y_pred,
                            const float* __restrict__ y_true,
                            const float* __restrict__ Lam,
                            float* __restrict__ out_all) {
    const int t = threadIdx.x;
    const int lane = t & 31;
    const int wid = t >> 5;

    extern __shared__ float4 dbuf[];  // [0,NF4) yp | [NF4,2NF4) yt | [2NF4,3NF4) Lam
    float4* byp  = dbuf;
    float4* byt  = dbuf + NF4;
    float4* blam = dbuf + 2 * NF4;
    const uint32_t byp_u32  = smem_u32(byp);
    const uint32_t byt_u32  = byp_u32 + NF4 * 16;
    const uint32_t blam_u32 = byp_u32 + 2 * NF4 * 16;

    __shared__ float s1s[32];   // 16 warp partials + 16 zero-pad
    __shared__ float s2s[32];
    __shared__ float s3s[32];
    __shared__ float bc_beta;
    __shared__ float bc_max;
    __shared__ int   sdone;
    __shared__ int   amLast;

    if (t >= NWARP && t < 32) { s1s[t] = 0.0f; s2s[t] = 0.0f; s3s[t] = 0.0f; }

    float* out_lambda = out_all + 1;
    float4* out4 = (float4*)out_all;   // out_all is 16B-aligned

    // ---- prologue: stage row0's y (group A0) then Lam (group L0) ----
    {
        const size_t nb4 = (size_t)blockIdx.x * (N / 4);
        const float4* gyp = (const float4*)y_pred + nb4;
        const float4* gyt = (const float4*)y_true + nb4;
        const float4* glm = (const float4*)Lam + nb4;
#pragma unroll
        for (int c = 0; c < 4; c++) {
            const int idx = t + c * BDIM;
            cp16(byp_u32 + idx * 16, gyp + idx);
            cp16(byt_u32 + idx * 16, gyt + idx);
        }
        asm volatile("cp.async.commit_group;" ::: "memory");
#pragma unroll
        for (int c = 0; c < 4; c++) {
            const int idx = t + c * BDIM;
            cp16(blam_u32 + idx * 16, glm + idx);
        }
        asm volatile("cp.async.commit_group;" ::: "memory");
    }

    float loss_acc = 0.0f;

#pragma unroll 1
    for (int row = blockIdx.x; row < B; row += NCTA) {
        const size_t base = (size_t)row * N;
        const int nrow = row + NCTA;

        // ---- wait for this row's y (all but newest group = y_k) ----
        asm volatile("cp.async.wait_group 1;" ::: "memory");
        float r[VPT];
#pragma unroll
        for (int c = 0; c < 4; c++) {
            const float4 p = byp[t + c * BDIM];
            const float4 g = byt[t + c * BDIM];
            r[4 * c + 0] = fabsf(g.x - p.x);
            r[4 * c + 1] = fabsf(g.y - p.y);
            r[4 * c + 2] = fabsf(g.z - p.z);
            r[4 * c + 3] = fabsf(g.w - p.w);
        }

        // ---- stage NEXT row's y (self-partition; group A_{k+1}) ----
        if (nrow < B) {
            const size_t nb4 = (size_t)nrow * (N / 4);
            const float4* gyp = (const float4*)y_pred + nb4;
            const float4* gyt = (const float4*)y_true + nb4;
#pragma unroll
            for (int c = 0; c < 4; c++) {
                const int idx = t + c * BDIM;
                cp16(byp_u32 + idx * 16, gyp + idx);
                cp16(byt_u32 + idx * 16, gyt + idx);
            }
            asm volatile("cp.async.commit_group;" ::: "memory");
        }

        // ---- THE barrier round: rmax + S,T at the constant init beta_c ----
        float m = 0.0f, S = 0.0f, T = 0.0f;
#pragma unroll
        for (int i = 0; i < VPT; i++) {
            m = fmaxf(m, r[i]);
            const float x  = BETA_C * r[i];
            const float E  = __expf(x);
            const float Em = __expf(-x);
            S += (E - Em);
            T = fmaf(E + Em, r[i], T);
        }
        m = warp_max(m);
        S = warp_sum(S);
        T = warp_sum(T);
        if (lane == 0) { s1s[wid] = m; s2s[wid] = S; s3s[wid] = T; }
        __syncthreads();
        if (t < 32) {
            const float vm = warp_max(s1s[lane]);
            const float S2 = warp_sum(s2s[lane]);
            const float T2 = warp_sum(s3s[lane]);
            if (t == 0) {
                const float h  = __logf(S2) - LOG_2N;
                const float db = h * __fdividef(S2, T2);
                float nb = BETA_C - db;
                bc_beta = fminf(fmaxf(nb, 0.05f * BETA_C), 4.0f * BETA_C);
                bc_max  = vm;
                sdone   = (fabsf(db) < 2e-2f * BETA_C) ? 1 : 0;
            }
        }
        __syncthreads();
        float beta = bc_beta;
        const float rmax = bc_max;

        // ---- adaptive extra polish (normally skipped entirely) ----
        if (!sdone) {
#pragma unroll 1
            for (int itn = 0; itn < 10; itn++) {
                float Sa = 0.0f, Ta = 0.0f;
#pragma unroll
                for (int i = 0; i < VPT; i++) {
                    const float x  = beta * r[i];
                    const float E  = __expf(x);
                    const float Em = __expf(-x);
                    Sa += (E - Em);
                    Ta = fmaf(E + Em, r[i], Ta);
                }
                Sa = warp_sum(Sa);
                Ta = warp_sum(Ta);
                if (lane == 0) { s2s[wid] = Sa; s3s[wid] = Ta; }
                __syncthreads();
                if (t < 32) {
                    const float S2 = warp_sum(s2s[lane]);
                    const float T2 = warp_sum(s3s[lane]);
                    if (t == 0) {
                        const float h  = __logf(S2) - LOG_2N;
                        const float db = h * __fdividef(S2, T2);
                        float nb = beta - db;
                        bc_beta = fminf(fmaxf(nb, 0.05f * beta), 4.0f * beta);
                        sdone = (fabsf(db) < 2e-2f * beta) ? 1 : 0;
                    }
                }
                __syncthreads();
                beta = bc_beta;
                if (sdone) break;
            }
        }

        // ---- final beta exactly as reference: eps floor, then +1e-6 ----
        const float eps = fmaxf(__fdividef(1.0f, beta), 1e-8f);
        const float betaF = __fdividef(1.0f, eps + 1e-6f);
        const float xm = betaF * rmax;
        const float qmax = 0.5f * (__expf(xm) - __expf(-xm));
        const float c1 = __fdividef(0.045f, qmax + 1e-20f);

        // ---- wait for this row's Lam (all but newest group = L_k) ----
        if (nrow < B) {
            asm volatile("cp.async.wait_group 1;" ::: "memory");
        } else {
            asm volatile("cp.async.wait_group 0;" ::: "memory");
        }

        // ---- epilogue: lam from smem only; shuffled aligned stores ----
        const size_t orow4 = (size_t)row * (N / 4);  // out4 base of this row
#pragma unroll
        for (int c = 0; c < 4; c++) {
            const int j = t + c * BDIM;          // col group 4j..4j+3
            const float4 l = blam[j];
            const float la[4] = {l.x, l.y, l.z, l.w};
            float lamv[4];
#pragma unroll
            for (int i = 0; i < 4; i++) {
                const float rv = r[4 * c + i];
                const float x  = betaF * rv;
                const float E  = __expf(x);
                const float Em = __expf(-x);
                lamv[i] = fmaf(0.99f, la[i], fmaf(c1, E - Em, 0.01f));
                const float z = lamv[i] * rv;
                loss_acc = fmaf(z, z, loss_acc);
            }
            // aligned float4 at out offset 4j+4 = {my lam3, next lam0,1,2}
            const float n0 = __shfl_down_sync(0xffffffffu, lamv[0], 1);
            const float n1 = __shfl_down_sync(0xffffffffu, lamv[1], 1);
            const float n2 = __shfl_down_sync(0xffffffffu, lamv[2], 1);
            if (lane < 31) {
                const float4 v = make_float4(lamv[3], n0, n1, n2);
                __stcs(&out4[orow4 + j + 1], v);
            } else {
                __stcs(&out_lambda[base + 4 * j + 3], lamv[3]);
            }
            if (lane == 0) {
                __stcs(&out_lambda[base + 4 * j + 0], lamv[0]);
                __stcs(&out_lambda[base + 4 * j + 1], lamv[1]);
                __stcs(&out_lambda[base + 4 * j + 2], lamv[2]);
            }
        }

        // ---- stage NEXT row's Lam (slots just consumed by this thread) ----
        if (nrow < B) {
            const size_t nb4 = (size_t)nrow * (N / 4);
            const float4* glm = (const float4*)Lam + nb4;
#pragma unroll
            for (int c = 0; c < 4; c++) {
                const int idx = t + c * BDIM;
                cp16(blam_u32 + idx * 16, glm + idx);
            }
            asm volatile("cp.async.commit_group;" ::: "memory");
        }
    }

    // ---- end of rows: one block reduction of the register accumulator ----
    {
        float ls = warp_sum(loss_acc);
        __syncthreads();
        if (lane == 0) s1s[wid] = ls;
        __syncthreads();
        if (t == 0) {
            float v = 0.0f;
#pragma unroll
            for (int i = 0; i < NWARP; i++) v += s1s[i];
            g_cta_loss[blockIdx.x] = v;
        }
    }

    // ---- fused final reduction: last CTA reduces 296 partials, fixed order
    if (t == 0) {
        __threadfence();
        const unsigned int v = atomicAdd(&g_count, 1u);
        amLast = (v == (unsigned int)(NCTA - 1));
    }
    __syncthreads();
    if (amLast) {
        float s = (t < NCTA) ? g_cta_loss[t] : 0.0f;
        s = warp_sum(s);
        if (lane == 0) s2s[wid] = s;   // 16 partials; slots 16..31 still 0
        __syncthreads();
        if (t < 32) {
            const float v = warp_sum(s2s[lane]);
            if (t == 0) {
                out_all[0] = v * (1.0f / 16777216.0f);  // / (B*N)
                g_count = 0;  // reset for the next launch / graph replay
            }
        }
    }
}

extern "C" void kernel_launch(void* const* d_in, const int* in_sizes, int n_in,
                              void* d_out, int out_size) {
    const float* y_pred = (const float*)d_in[0];
    const float* y_true = (const float*)d_in[1];
    const float* Lam    = (const float*)d_in[2];
    // d_in[3] = it (unused by the cosh branch)

    const int dyn_smem = 3 * NF4 * 16;  // 96 KB (yp + yt + Lam staging)
    cudaFuncSetAttribute(custom_loss_row_kernel,
                         cudaFuncAttributeMaxDynamicSharedMemorySize, dyn_smem);
    custom_loss_row_kernel<<<NCTA, BDIM, dyn_smem>>>(y_pred, y_true, Lam,
                                                     (float*)d_out);
}